// round 1
// baseline (speedup 1.0000x reference)
#include <cuda_runtime.h>

#define NGn 50000
#define NDn 10000
#define INF 64
#define HIDF 128
#define E_GG 800000
#define E_GD 300000
#define E_DG 300000

// ---------------- static scratch ----------------
__device__ int g_cnt[NGn];
__device__ int g_pos[NGn];
__device__ int g_rp_gg[NGn + 1];
__device__ int g_rp_dg[NGn + 1];
__device__ int g_rp_gd[NDn + 1];
__device__ int g_col_gg[E_GG];
__device__ int g_col_dg[E_DG];
__device__ int g_col_gd[E_GD];

__device__ float g_mgg[NGn * HIDF];
__device__ float g_mdg[NGn * HIDF];
__device__ float g_mgd[NDn * HIDF];
__device__ float g_hgA[NGn * HIDF];
__device__ float g_hdA[NDn * HIDF];
__device__ float g_hgB[NGn * HIDF];
__device__ float g_hdB[NDn * HIDF];

__device__ float g_Wself0[INF * HIDF];
__device__ float g_Wself1[HIDF * HIDF];
__device__ float g_bsum0[HIDF];
__device__ float g_bsum1[HIDF];
__device__ float g_colsum[HIDF];
__device__ float g_colsq[HIDF];
__device__ float g_scale[HIDF];
__device__ float g_shift[HIDF];

// ---------------- small utility kernels ----------------
__global__ void k_zero_int(int* p, int n) {
    int i = blockIdx.x * blockDim.x + threadIdx.x;
    if (i < n) p[i] = 0;
}

__global__ void k_copy_int(const int* __restrict__ a, int* __restrict__ b, int n) {
    int i = blockIdx.x * blockDim.x + threadIdx.x;
    if (i < n) b[i] = a[i];
}

__global__ void k_hist(const int* __restrict__ dst, int e, int* __restrict__ cnt) {
    int i = blockIdx.x * blockDim.x + threadIdx.x;
    if (i < e) atomicAdd(&cnt[dst[i]], 1);
}

// single-block exclusive scan, n up to ~50001. rp has n+1 entries.
__global__ void k_scan(const int* __restrict__ cnt, int* __restrict__ rp, int n) {
    __shared__ int s[1024];
    __shared__ int carry;
    if (threadIdx.x == 0) carry = 0;
    __syncthreads();
    for (int base = 0; base < n; base += 1024) {
        int i = base + threadIdx.x;
        int v = (i < n) ? cnt[i] : 0;
        s[threadIdx.x] = v;
        __syncthreads();
        for (int off = 1; off < 1024; off <<= 1) {
            int t = (threadIdx.x >= off) ? s[threadIdx.x - off] : 0;
            __syncthreads();
            s[threadIdx.x] += t;
            __syncthreads();
        }
        if (i < n) rp[i] = carry + s[threadIdx.x] - v;
        __syncthreads();
        if (threadIdx.x == 1023) carry += s[1023];
        __syncthreads();
    }
    if (threadIdx.x == 0) rp[n] = carry;
}

__global__ void k_scatter(const int* __restrict__ src, const int* __restrict__ dst,
                          int e, int* __restrict__ pos, int* __restrict__ col) {
    int i = blockIdx.x * blockDim.x + threadIdx.x;
    if (i < e) {
        int p = atomicAdd(&pos[dst[i]], 1);
        col[p] = src[i];
    }
}

__global__ void k_add2(const float* __restrict__ a, const float* __restrict__ b,
                       float* __restrict__ o, int n) {
    int i = blockIdx.x * blockDim.x + threadIdx.x;
    if (i < n) o[i] = a[i] + b[i];
}

// ---------------- mean aggregation over CSR ----------------
// one group of F/4 threads per destination node, float4 per lane
template <int F>
__global__ void k_agg_mean(const float* __restrict__ hsrc, const int* __restrict__ rp,
                           const int* __restrict__ col, float* __restrict__ out, int ndst) {
    constexpr int G = F / 4;
    int gpb = blockDim.x / G;
    int node = blockIdx.x * gpb + (threadIdx.x / G);
    int lane = threadIdx.x % G;
    if (node >= ndst) return;
    int s = rp[node];
    int e = rp[node + 1];
    float4 acc = make_float4(0.f, 0.f, 0.f, 0.f);
    for (int i = s; i < e; i++) {
        int sidx = __ldg(&col[i]);
        float4 v = __ldg((const float4*)&hsrc[(long)sidx * F + lane * 4]);
        acc.x += v.x; acc.y += v.y; acc.z += v.z; acc.w += v.w;
    }
    float inv = (e > s) ? 1.f / (float)(e - s) : 0.f;
    acc.x *= inv; acc.y *= inv; acc.z *= inv; acc.w *= inv;
    ((float4*)&out[(long)node * F])[lane] = acc;
}

// ---------------- multi-panel SGEMM ----------------
// C[M,BN] = sum_p A_p[M,K] @ W_p[K,BN] + bias[BN]
// BM=128, TM=8, BK=16, threads = 16*(BN/TN) = 256
template <int BN, int TN>
__global__ void __launch_bounds__(256)
k_gemm(const float* __restrict__ A0, const float* __restrict__ A1, const float* __restrict__ A2,
       const float* __restrict__ W0, const float* __restrict__ W1, const float* __restrict__ W2,
       const float* __restrict__ bias, float* __restrict__ C, int M, int K, int npan) {
    constexpr int BM = 128;
    constexpr int TM = 8;
    constexpr int BK = 16;
    __shared__ float As[BK][BM + 4];
    __shared__ float Ws[BK][BN];

    int tid = threadIdx.x;
    int tx = tid % (BN / TN);
    int ty = tid / (BN / TN);
    int rowBase = blockIdx.x * BM;

    float acc[TM][TN];
#pragma unroll
    for (int i = 0; i < TM; i++)
#pragma unroll
        for (int j = 0; j < TN; j++) acc[i][j] = 0.f;

    const float* Ap[3] = {A0, A1, A2};
    const float* Wp[3] = {W0, W1, W2};

    for (int p = 0; p < npan; p++) {
        const float* A = Ap[p];
        const float* W = Wp[p];
        for (int kt = 0; kt < K; kt += BK) {
            // load A tile (BM x BK), transposed into As
#pragma unroll
            for (int f = tid; f < BM * BK / 4; f += 256) {
                int r = f >> 2;       // BK/4 = 4 float4 per row
                int c4 = f & 3;
                float4 v = make_float4(0.f, 0.f, 0.f, 0.f);
                int row = rowBase + r;
                if (row < M) v = *(const float4*)&A[(long)row * K + kt + c4 * 4];
                As[c4 * 4 + 0][r] = v.x;
                As[c4 * 4 + 1][r] = v.y;
                As[c4 * 4 + 2][r] = v.z;
                As[c4 * 4 + 3][r] = v.w;
            }
            // load W tile (BK x BN)
#pragma unroll
            for (int f = tid; f < BK * BN / 4; f += 256) {
                int r = f / (BN / 4);
                int c4 = f % (BN / 4);
                *(float4*)&Ws[r][c4 * 4] = *(const float4*)&W[(long)(kt + r) * BN + c4 * 4];
            }
            __syncthreads();
#pragma unroll
            for (int kk = 0; kk < BK; kk++) {
                float ra[TM], rb[TN];
#pragma unroll
                for (int i = 0; i < TM; i++) ra[i] = As[kk][ty * TM + i];
#pragma unroll
                for (int j = 0; j < TN; j++) rb[j] = Ws[kk][tx * TN + j];
#pragma unroll
                for (int i = 0; i < TM; i++)
#pragma unroll
                    for (int j = 0; j < TN; j++) acc[i][j] = fmaf(ra[i], rb[j], acc[i][j]);
            }
            __syncthreads();
        }
    }

    // epilogue
#pragma unroll
    for (int i = 0; i < TM; i++) {
        int row = rowBase + ty * TM + i;
        if (row >= M) continue;
#pragma unroll
        for (int j4 = 0; j4 < TN; j4 += 4) {
            int colb = tx * TN + j4;
            float4 v;
            v.x = acc[i][j4 + 0] + bias[colb + 0];
            v.y = acc[i][j4 + 1] + bias[colb + 1];
            v.z = acc[i][j4 + 2] + bias[colb + 2];
            v.w = acc[i][j4 + 3] + bias[colb + 3];
            *(float4*)&C[(long)row * BN + colb] = v;
        }
    }
}

// ---------------- BatchNorm helpers ----------------
__global__ void k_zero_stats(float* s, float* q) {
    if (threadIdx.x < HIDF) { s[threadIdx.x] = 0.f; q[threadIdx.x] = 0.f; }
}

__global__ void k_col_stats(const float* __restrict__ X, int M,
                            float* __restrict__ sum, float* __restrict__ sq) {
    int c = threadIdx.x;  // 128 threads
    int r0 = blockIdx.x * 256;
    int r1 = r0 + 256;
    if (r1 > M) r1 = M;
    float s = 0.f, q = 0.f;
    for (int r = r0; r < r1; r++) {
        float v = X[(long)r * HIDF + c];
        s += v;
        q = fmaf(v, v, q);
    }
    atomicAdd(&sum[c], s);
    atomicAdd(&sq[c], q);
}

__global__ void k_bn_finalize(const float* __restrict__ sum, const float* __restrict__ sq,
                              float Mf, const float* __restrict__ g, const float* __restrict__ b,
                              float* __restrict__ scale, float* __restrict__ shift) {
    int c = threadIdx.x;
    float mu = sum[c] / Mf;
    float var = sq[c] / Mf - mu * mu;
    float sc = g[c] * rsqrtf(var + 1e-5f);
    scale[c] = sc;
    shift[c] = b[c] - mu * sc;
}

__global__ void k_bn_relu(float* __restrict__ X, int n4,
                          const float* __restrict__ scale, const float* __restrict__ shift) {
    int i = blockIdx.x * blockDim.x + threadIdx.x;
    if (i >= n4) return;
    float4 v = ((float4*)X)[i];
    int c = (i & 31) * 4;  // row = 128 floats = 32 float4
    v.x = fmaxf(0.f, fmaf(v.x, scale[c + 0], shift[c + 0]));
    v.y = fmaxf(0.f, fmaf(v.y, scale[c + 1], shift[c + 1]));
    v.z = fmaxf(0.f, fmaf(v.z, scale[c + 2], shift[c + 2]));
    v.w = fmaxf(0.f, fmaf(v.w, scale[c + 3], shift[c + 3]));
    ((float4*)X)[i] = v;
}

// ---------------- host side ----------------
template <typename T>
static T* sym(const void* s) {
    void* p = nullptr;
    cudaGetSymbolAddress(&p, s);
    return (T*)p;
}

extern "C" void kernel_launch(void* const* d_in, const int* in_sizes, int n_in,
                              void* d_out, int out_size) {
    const float* xg  = (const float*)d_in[0];
    const float* xd  = (const float*)d_in[1];
    const float* Wn0 = (const float*)d_in[2];
    const float* Ws0 = (const float*)d_in[3];
    const float* b0  = (const float*)d_in[4];
    const float* Wn1 = (const float*)d_in[5];
    const float* Ws1 = (const float*)d_in[6];
    const float* b1  = (const float*)d_in[7];
    const float* bng = (const float*)d_in[8];
    const float* bnb = (const float*)d_in[9];
    const float* Wpm = (const float*)d_in[10];
    const float* bp  = (const float*)d_in[11];
    const int* gg_src = (const int*)d_in[12];
    const int* gg_dst = (const int*)d_in[13];
    const int* gd_src = (const int*)d_in[14];
    const int* gd_dst = (const int*)d_in[15];
    const int* dg_src = (const int*)d_in[16];
    const int* dg_dst = (const int*)d_in[17];

    const int NG = in_sizes[0] / INF;
    const int ND = in_sizes[1] / INF;
    const int egg = in_sizes[12];
    const int egd = in_sizes[14];
    const int edg = in_sizes[16];

    float* out = (float*)d_out;

    int* cnt = sym<int>(g_cnt);
    int* pos = sym<int>(g_pos);
    int* rp_gg = sym<int>(g_rp_gg);
    int* rp_dg = sym<int>(g_rp_dg);
    int* rp_gd = sym<int>(g_rp_gd);
    int* col_gg = sym<int>(g_col_gg);
    int* col_dg = sym<int>(g_col_dg);
    int* col_gd = sym<int>(g_col_gd);
    float* mgg = sym<float>(g_mgg);
    float* mdg = sym<float>(g_mdg);
    float* mgd = sym<float>(g_mgd);
    float* hgA = sym<float>(g_hgA);
    float* hdA = sym<float>(g_hdA);
    float* hgB = sym<float>(g_hgB);
    float* hdB = sym<float>(g_hdB);
    float* Wself0 = sym<float>(g_Wself0);
    float* Wself1 = sym<float>(g_Wself1);
    float* bsum0 = sym<float>(g_bsum0);
    float* bsum1 = sym<float>(g_bsum1);
    float* colsum = sym<float>(g_colsum);
    float* colsq = sym<float>(g_colsq);
    float* scale = sym<float>(g_scale);
    float* shift = sym<float>(g_shift);

    auto cdiv = [](int a, int b) { return (a + b - 1) / b; };

    // --- combined self weights / biases ---
    k_add2<<<cdiv(INF * HIDF, 256), 256>>>(Ws0, Ws0 + 2 * INF * HIDF, Wself0, INF * HIDF);
    k_add2<<<cdiv(HIDF * HIDF, 256), 256>>>(Ws1, Ws1 + 2 * HIDF * HIDF, Wself1, HIDF * HIDF);
    k_add2<<<1, 128>>>(b0, b0 + 2 * HIDF, bsum0, HIDF);
    k_add2<<<1, 128>>>(b1, b1 + 2 * HIDF, bsum1, HIDF);

    // --- build CSR (by destination) for each edge type ---
    auto buildCSR = [&](const int* src, const int* dst, int e, int n, int* rp, int* col) {
        k_zero_int<<<cdiv(n, 256), 256>>>(cnt, n);
        k_hist<<<cdiv(e, 256), 256>>>(dst, e, cnt);
        k_scan<<<1, 1024>>>(cnt, rp, n);
        k_copy_int<<<cdiv(n, 256), 256>>>(rp, pos, n);
        k_scatter<<<cdiv(e, 256), 256>>>(src, dst, e, pos, col);
    };
    buildCSR(gg_src, gg_dst, egg, NG, rp_gg, col_gg);
    buildCSR(dg_src, dg_dst, edg, NG, rp_dg, col_dg);
    buildCSR(gd_src, gd_dst, egd, ND, rp_gd, col_gd);

    auto bn = [&](float* X, int M, const float* g, const float* b) {
        k_zero_stats<<<1, 128>>>(colsum, colsq);
        k_col_stats<<<cdiv(M, 256), 128>>>(X, M, colsum, colsq);
        k_bn_finalize<<<1, 128>>>(colsum, colsq, (float)M, g, b, scale, shift);
        k_bn_relu<<<cdiv(M * HIDF / 4, 256), 256>>>(X, M * HIDF / 4, scale, shift);
    };

    // ---------- layer 0 (F = 64) ----------
    {
        constexpr int G = INF / 4;          // 16 threads per node
        int npb = 256 / G;
        k_agg_mean<INF><<<cdiv(NG, npb), 256>>>(xg, rp_gg, col_gg, mgg, NG);
        k_agg_mean<INF><<<cdiv(NG, npb), 256>>>(xd, rp_dg, col_dg, mdg, NG);
        k_agg_mean<INF><<<cdiv(ND, npb), 256>>>(xg, rp_gd, col_gd, mgd, ND);
    }
    // genes: mgg@Wn0[0] + mdg@Wn0[2] + xg@(Ws0[0]+Ws0[2]) + (b0[0]+b0[2])
    k_gemm<HIDF, 8><<<cdiv(NG, 128), 256>>>(mgg, mdg, xg,
        Wn0, Wn0 + 2 * INF * HIDF, Wself0, bsum0, hgA, NG, INF, 3);
    // diseases: mgd@Wn0[1] + xd@Ws0[1] + b0[1]
    k_gemm<HIDF, 8><<<cdiv(ND, 128), 256>>>(mgd, xd, nullptr,
        Wn0 + INF * HIDF, Ws0 + INF * HIDF, nullptr, b0 + HIDF, hdA, ND, INF, 2);
    bn(hgA, NG, bng + 0 * HIDF, bnb + 0 * HIDF);
    bn(hdA, ND, bng + 1 * HIDF, bnb + 1 * HIDF);

    // ---------- layer 1 (F = 128) ----------
    {
        constexpr int G = HIDF / 4;         // 32 threads per node
        int npb = 256 / G;
        k_agg_mean<HIDF><<<cdiv(NG, npb), 256>>>(hgA, rp_gg, col_gg, mgg, NG);
        k_agg_mean<HIDF><<<cdiv(NG, npb), 256>>>(hdA, rp_dg, col_dg, mdg, NG);
        k_agg_mean<HIDF><<<cdiv(ND, npb), 256>>>(hgA, rp_gd, col_gd, mgd, ND);
    }
    k_gemm<HIDF, 8><<<cdiv(NG, 128), 256>>>(mgg, mdg, hgA,
        Wn1, Wn1 + 2 * HIDF * HIDF, Wself1, bsum1, hgB, NG, HIDF, 3);
    k_gemm<HIDF, 8><<<cdiv(ND, 128), 256>>>(mgd, hdA, nullptr,
        Wn1 + HIDF * HIDF, Ws1 + HIDF * HIDF, nullptr, b1 + HIDF, hdB, ND, HIDF, 2);
    bn(hgB, NG, bng + 2 * HIDF, bnb + 2 * HIDF);
    bn(hdB, ND, bng + 3 * HIDF, bnb + 3 * HIDF);

    // ---------- final projection (N = 64) ----------
    k_gemm<INF, 4><<<cdiv(NG, 128), 256>>>(hgB, nullptr, nullptr,
        Wpm, nullptr, nullptr, bp, out, NG, HIDF, 1);
    k_gemm<INF, 4><<<cdiv(ND, 128), 256>>>(hdB, nullptr, nullptr,
        Wpm + HIDF * INF, nullptr, nullptr, bp + INF, out + (long)NG * INF, ND, HIDF, 1);
}

// round 2
// speedup vs baseline: 1.2568x; 1.2568x over previous
#include <cuda_runtime.h>

#define NGn 50000
#define NDn 10000
#define INF 64
#define HIDF 128
#define E_GG 800000
#define E_GD 300000
#define E_DG 300000

// ---------------- static scratch ----------------
__device__ int g_cnt_gg[NGn];
__device__ int g_cnt_dg[NGn];
__device__ int g_cnt_gd[NDn];
__device__ int g_pos_gg[NGn];
__device__ int g_pos_dg[NGn];
__device__ int g_pos_gd[NDn];
__device__ int g_rp_gg[NGn + 1];
__device__ int g_rp_dg[NGn + 1];
__device__ int g_rp_gd[NDn + 1];
__device__ int g_col_gg[E_GG];
__device__ int g_col_dg[E_DG];
__device__ int g_col_gd[E_GD];
__device__ int g_part[256];

__device__ float g_mgg[NGn * HIDF];
__device__ float g_mdg[NGn * HIDF];
__device__ float g_mgd[NDn * HIDF];
__device__ float g_hgA[NGn * HIDF];
__device__ float g_hdA[NDn * HIDF];
__device__ float g_hgB[NGn * HIDF];
__device__ float g_hdB[NDn * HIDF];

__device__ float g_Wself0[INF * HIDF];
__device__ float g_Wself1[HIDF * HIDF];
__device__ float g_bsum0[HIDF];
__device__ float g_bsum1[HIDF];
__device__ float g_colsum[HIDF];
__device__ float g_colsq[HIDF];
__device__ float g_scale[HIDF];
__device__ float g_shift[HIDF];

// ---------------- prep: fused weight/bias sums ----------------
__global__ void k_prep(const float* __restrict__ Ws0, const float* __restrict__ Ws1,
                       const float* __restrict__ b0, const float* __restrict__ b1,
                       float* __restrict__ Wself0, float* __restrict__ Wself1,
                       float* __restrict__ bsum0, float* __restrict__ bsum1) {
    int i = blockIdx.x * blockDim.x + threadIdx.x;
    if (i < INF * HIDF) Wself0[i] = Ws0[i] + Ws0[2 * INF * HIDF + i];
    if (i < HIDF * HIDF) Wself1[i] = Ws1[i] + Ws1[2 * HIDF * HIDF + i];
    if (i < HIDF) {
        bsum0[i] = b0[i] + b0[2 * HIDF + i];
        bsum1[i] = b1[i] + b1[2 * HIDF + i];
    }
}

// ---------------- CSR build kernels ----------------
__global__ void k_hist(const int* __restrict__ dst, int e, int* __restrict__ cnt) {
    int i = blockIdx.x * blockDim.x + threadIdx.x;
    if (i < e) atomicAdd(&cnt[dst[i]], 1);
}

// scan pass 1: per-1024-chunk sums
__global__ void k_scan_part(const int* __restrict__ cnt, int n, int* __restrict__ part) {
    __shared__ int s[1024];
    int i = blockIdx.x * 1024 + threadIdx.x;
    int v = (i < n) ? cnt[i] : 0;
    s[threadIdx.x] = v;
    __syncthreads();
    for (int off = 512; off > 0; off >>= 1) {
        if (threadIdx.x < off) s[threadIdx.x] += s[threadIdx.x + off];
        __syncthreads();
    }
    if (threadIdx.x == 0) part[blockIdx.x] = s[0];
}

// scan pass 2: exclusive scan of partials (nb <= 64), also writes rp[n]=total
__global__ void k_scan_mid(int* __restrict__ part, int nb, int* __restrict__ rp, int n) {
    __shared__ int s[64];
    int v = (threadIdx.x < nb) ? part[threadIdx.x] : 0;
    s[threadIdx.x] = v;
    __syncthreads();
    for (int off = 1; off < 64; off <<= 1) {
        int t = (threadIdx.x >= off) ? s[threadIdx.x - off] : 0;
        __syncthreads();
        s[threadIdx.x] += t;
        __syncthreads();
    }
    if (threadIdx.x < nb) part[threadIdx.x] = s[threadIdx.x] - v;  // exclusive
    if (threadIdx.x == 63) rp[n] = s[63];
}

// scan pass 3: per-chunk inclusive scan + offset -> exclusive rp
__global__ void k_scan_final(const int* __restrict__ cnt, int n,
                             const int* __restrict__ part, int* __restrict__ rp) {
    __shared__ int s[1024];
    int i = blockIdx.x * 1024 + threadIdx.x;
    int v = (i < n) ? cnt[i] : 0;
    s[threadIdx.x] = v;
    __syncthreads();
    for (int off = 1; off < 1024; off <<= 1) {
        int t = (threadIdx.x >= off) ? s[threadIdx.x - off] : 0;
        __syncthreads();
        s[threadIdx.x] += t;
        __syncthreads();
    }
    if (i < n) rp[i] = part[blockIdx.x] + s[threadIdx.x] - v;
}

__global__ void k_scatter(const int* __restrict__ src, const int* __restrict__ dst,
                          int e, int* __restrict__ pos, int* __restrict__ col) {
    int i = blockIdx.x * blockDim.x + threadIdx.x;
    if (i < e) {
        int p = atomicAdd(&pos[dst[i]], 1);
        col[p] = src[i];
    }
}

// ---------------- mean aggregation over CSR ----------------
template <int F>
__global__ void k_agg_mean(const float* __restrict__ hsrc, const int* __restrict__ rp,
                           const int* __restrict__ col, float* __restrict__ out, int ndst) {
    constexpr int G = F / 4;
    int gpb = blockDim.x / G;
    int node = blockIdx.x * gpb + (threadIdx.x / G);
    int lane = threadIdx.x % G;
    if (node >= ndst) return;
    int s = rp[node];
    int e = rp[node + 1];
    float4 acc = make_float4(0.f, 0.f, 0.f, 0.f);
    for (int i = s; i < e; i++) {
        int sidx = __ldg(&col[i]);
        float4 v = __ldg((const float4*)&hsrc[(long)sidx * F + lane * 4]);
        acc.x += v.x; acc.y += v.y; acc.z += v.z; acc.w += v.w;
    }
    float inv = (e > s) ? 1.f / (float)(e - s) : 0.f;
    acc.x *= inv; acc.y *= inv; acc.z *= inv; acc.w *= inv;
    ((float4*)&out[(long)node * F])[lane] = acc;
}

// ---------------- dual-problem multi-panel SGEMM ----------------
struct GemmProb {
    const float* A[3];
    const float* W[3];
    const float* bias;
    float* C;
    int M, K, npan;
};

// BM=128, BK=16, TM=8, 256 threads. Double-buffered smem + register prefetch.
template <int BN, int TN>
__global__ void __launch_bounds__(256, 2)
k_gemm_dual(GemmProb pa, GemmProb pb, int nb0) {
    constexpr int BM = 128;
    constexpr int BK = 16;
    constexpr int TM = 8;
    constexpr int LDA = BM + 4;
    constexpr int NW = (BK * BN / 4) / 256;   // W float4 loads per thread
    __shared__ float As[2][BK][LDA];
    __shared__ float Ws[2][BK][BN];

    bool second = (blockIdx.x >= nb0);
    GemmProb P = second ? pb : pa;
    int bid = second ? (blockIdx.x - nb0) : blockIdx.x;
    int rowBase = bid * BM;
    int tid = threadIdx.x;
    int tx = tid % (BN / TN);
    int ty = tid / (BN / TN);

    int ktiles = P.K / BK;
    int T = P.npan * ktiles;

    float acc[TM][TN];
#pragma unroll
    for (int i = 0; i < TM; i++)
#pragma unroll
        for (int j = 0; j < TN; j++) acc[i][j] = 0.f;

    float4 rA[2];
    float4 rW[NW];

    // A coords: f = tid + it*256 -> r = f>>2 (0..127), c4 = f&3
    int ar[2], ac4[2];
#pragma unroll
    for (int it = 0; it < 2; it++) {
        int f = tid + it * 256;
        ar[it] = f >> 2;
        ac4[it] = f & 3;
    }

    auto ldgTile = [&](int t) {
        int p = t / ktiles;
        int kt = (t - p * ktiles) * BK;
        const float* A = P.A[p];
        const float* W = P.W[p];
#pragma unroll
        for (int it = 0; it < 2; it++) {
            int row = rowBase + ar[it];
            if (row >= P.M) row = P.M - 1;   // clamp; OOB rows never written
            rA[it] = *(const float4*)&A[(long)row * P.K + kt + ac4[it] * 4];
        }
#pragma unroll
        for (int it = 0; it < NW; it++) {
            int f = tid + it * 256;
            int r = f / (BN / 4);
            int c4 = f % (BN / 4);
            rW[it] = *(const float4*)&W[(long)(kt + r) * BN + c4 * 4];
        }
    };

    ldgTile(0);
    for (int t = 0; t < T; t++) {
        int sbuf = t & 1;
        // store staged regs
#pragma unroll
        for (int it = 0; it < 2; it++) {
            As[sbuf][ac4[it] * 4 + 0][ar[it]] = rA[it].x;
            As[sbuf][ac4[it] * 4 + 1][ar[it]] = rA[it].y;
            As[sbuf][ac4[it] * 4 + 2][ar[it]] = rA[it].z;
            As[sbuf][ac4[it] * 4 + 3][ar[it]] = rA[it].w;
        }
#pragma unroll
        for (int it = 0; it < NW; it++) {
            int f = tid + it * 256;
            int r = f / (BN / 4);
            int c4 = f % (BN / 4);
            *(float4*)&Ws[sbuf][r][c4 * 4] = rW[it];
        }
        if (t + 1 < T) ldgTile(t + 1);
        __syncthreads();
#pragma unroll
        for (int kk = 0; kk < BK; kk++) {
            float ra[TM], rb[TN];
#pragma unroll
            for (int i = 0; i < TM; i += 4)
                *(float4*)&ra[i] = *(const float4*)&As[sbuf][kk][ty * TM + i];
#pragma unroll
            for (int j = 0; j < TN; j += 4)
                *(float4*)&rb[j] = *(const float4*)&Ws[sbuf][kk][tx * TN + j];
#pragma unroll
            for (int i = 0; i < TM; i++)
#pragma unroll
                for (int j = 0; j < TN; j++) acc[i][j] = fmaf(ra[i], rb[j], acc[i][j]);
        }
        __syncthreads();   // protects Ws/As[sbuf] from being overwritten at t+2? no:
        // NOTE: with reg-prefetch the STS of t+1 targets the OTHER buffer, and the
        // STS of t+2 (same buffer) happens after the barrier of iteration t+1, so a
        // single barrier per tile would suffice; the second barrier here guards the
        // case T==1 tail and costs little (kept for safety).
    }

    // epilogue: bias + write
#pragma unroll
    for (int i = 0; i < TM; i++) {
        int row = rowBase + ty * TM + i;
        if (row >= P.M) continue;
#pragma unroll
        for (int j4 = 0; j4 < TN; j4 += 4) {
            int colb = tx * TN + j4;
            float4 v;
            v.x = acc[i][j4 + 0] + P.bias[colb + 0];
            v.y = acc[i][j4 + 1] + P.bias[colb + 1];
            v.z = acc[i][j4 + 2] + P.bias[colb + 2];
            v.w = acc[i][j4 + 3] + P.bias[colb + 3];
            *(float4*)&P.C[(long)row * BN + colb] = v;
        }
    }
}

// ---------------- BatchNorm helpers ----------------
__global__ void k_zero_stats(float* s, float* q) {
    if (threadIdx.x < HIDF) { s[threadIdx.x] = 0.f; q[threadIdx.x] = 0.f; }
}

__global__ void k_col_stats(const float* __restrict__ X, int M,
                            float* __restrict__ sum, float* __restrict__ sq) {
    int c = threadIdx.x;  // 128 threads
    int r0 = blockIdx.x * 512;
    int r1 = r0 + 512;
    if (r1 > M) r1 = M;
    float s = 0.f, q = 0.f;
    for (int r = r0; r < r1; r++) {
        float v = X[(long)r * HIDF + c];
        s += v;
        q = fmaf(v, v, q);
    }
    atomicAdd(&sum[c], s);
    atomicAdd(&sq[c], q);
}

__global__ void k_bn_finalize(const float* __restrict__ sum, const float* __restrict__ sq,
                              float Mf, const float* __restrict__ g, const float* __restrict__ b,
                              float* __restrict__ scale, float* __restrict__ shift) {
    int c = threadIdx.x;
    float mu = sum[c] / Mf;
    float var = sq[c] / Mf - mu * mu;
    float sc = g[c] * rsqrtf(var + 1e-5f);
    scale[c] = sc;
    shift[c] = b[c] - mu * sc;
}

__global__ void k_bn_relu(float* __restrict__ X, int n4,
                          const float* __restrict__ scale, const float* __restrict__ shift) {
    int i = blockIdx.x * blockDim.x + threadIdx.x;
    if (i >= n4) return;
    float4 v = ((float4*)X)[i];
    int c = (i & 31) * 4;  // 32 float4 per 128-wide row
    v.x = fmaxf(0.f, fmaf(v.x, __ldg(&scale[c + 0]), __ldg(&shift[c + 0])));
    v.y = fmaxf(0.f, fmaf(v.y, __ldg(&scale[c + 1]), __ldg(&shift[c + 1])));
    v.z = fmaxf(0.f, fmaf(v.z, __ldg(&scale[c + 2]), __ldg(&shift[c + 2])));
    v.w = fmaxf(0.f, fmaf(v.w, __ldg(&scale[c + 3]), __ldg(&shift[c + 3])));
    ((float4*)X)[i] = v;
}

// ---------------- host side ----------------
template <typename T>
static T* sym(const void* s) {
    void* p = nullptr;
    cudaGetSymbolAddress(&p, s);
    return (T*)p;
}

extern "C" void kernel_launch(void* const* d_in, const int* in_sizes, int n_in,
                              void* d_out, int out_size) {
    const float* xg  = (const float*)d_in[0];
    const float* xd  = (const float*)d_in[1];
    const float* Wn0 = (const float*)d_in[2];
    const float* Ws0 = (const float*)d_in[3];
    const float* b0  = (const float*)d_in[4];
    const float* Wn1 = (const float*)d_in[5];
    const float* Ws1 = (const float*)d_in[6];
    const float* b1  = (const float*)d_in[7];
    const float* bng = (const float*)d_in[8];
    const float* bnb = (const float*)d_in[9];
    const float* Wpm = (const float*)d_in[10];
    const float* bp  = (const float*)d_in[11];
    const int* gg_src = (const int*)d_in[12];
    const int* gg_dst = (const int*)d_in[13];
    const int* gd_src = (const int*)d_in[14];
    const int* gd_dst = (const int*)d_in[15];
    const int* dg_src = (const int*)d_in[16];
    const int* dg_dst = (const int*)d_in[17];

    const int NG = in_sizes[0] / INF;
    const int ND = in_sizes[1] / INF;
    const int egg = in_sizes[12];
    const int egd = in_sizes[14];
    const int edg = in_sizes[16];

    float* out = (float*)d_out;

    int* cnt_gg = sym<int>(g_cnt_gg);
    int* cnt_dg = sym<int>(g_cnt_dg);
    int* cnt_gd = sym<int>(g_cnt_gd);
    int* pos_gg = sym<int>(g_pos_gg);
    int* pos_dg = sym<int>(g_pos_dg);
    int* pos_gd = sym<int>(g_pos_gd);
    int* rp_gg = sym<int>(g_rp_gg);
    int* rp_dg = sym<int>(g_rp_dg);
    int* rp_gd = sym<int>(g_rp_gd);
    int* col_gg = sym<int>(g_col_gg);
    int* col_dg = sym<int>(g_col_dg);
    int* col_gd = sym<int>(g_col_gd);
    int* part = sym<int>(g_part);
    float* mgg = sym<float>(g_mgg);
    float* mdg = sym<float>(g_mdg);
    float* mgd = sym<float>(g_mgd);
    float* hgA = sym<float>(g_hgA);
    float* hdA = sym<float>(g_hdA);
    float* hgB = sym<float>(g_hgB);
    float* hdB = sym<float>(g_hdB);
    float* Wself0 = sym<float>(g_Wself0);
    float* Wself1 = sym<float>(g_Wself1);
    float* bsum0 = sym<float>(g_bsum0);
    float* bsum1 = sym<float>(g_bsum1);
    float* colsum = sym<float>(g_colsum);
    float* colsq = sym<float>(g_colsq);
    float* scale = sym<float>(g_scale);
    float* shift = sym<float>(g_shift);

    auto cdiv = [](int a, int b) { return (a + b - 1) / b; };

    // --- fused weight/bias prep ---
    k_prep<<<cdiv(HIDF * HIDF, 256), 256>>>(Ws0, Ws1, b0, b1, Wself0, Wself1, bsum0, bsum1);

    // --- build CSR (by destination) for each edge type ---
    auto buildCSR = [&](const int* src, const int* dst, int e, int n,
                        int* cnt, int* pos, int* rp, int* col) {
        cudaMemsetAsync(cnt, 0, n * sizeof(int));
        k_hist<<<cdiv(e, 256), 256>>>(dst, e, cnt);
        int nb = cdiv(n, 1024);
        k_scan_part<<<nb, 1024>>>(cnt, n, part);
        k_scan_mid<<<1, 64>>>(part, nb, rp, n);
        k_scan_final<<<nb, 1024>>>(cnt, n, part, rp);
        cudaMemcpyAsync(pos, rp, n * sizeof(int), cudaMemcpyDeviceToDevice);
        k_scatter<<<cdiv(e, 256), 256>>>(src, dst, e, pos, col);
    };
    buildCSR(gg_src, gg_dst, egg, NG, cnt_gg, pos_gg, rp_gg, col_gg);
    buildCSR(dg_src, dg_dst, edg, NG, cnt_dg, pos_dg, rp_dg, col_dg);
    buildCSR(gd_src, gd_dst, egd, ND, cnt_gd, pos_gd, rp_gd, col_gd);

    auto bn = [&](float* X, int M, const float* g, const float* b) {
        k_zero_stats<<<1, 128>>>(colsum, colsq);
        k_col_stats<<<cdiv(M, 512), 128>>>(X, M, colsum, colsq);
        k_bn_finalize<<<1, 128>>>(colsum, colsq, (float)M, g, b, scale, shift);
        k_bn_relu<<<cdiv(M * HIDF / 4, 256), 256>>>(X, M * HIDF / 4, scale, shift);
    };

    int nbG = cdiv(NG, 128);
    int nbD = cdiv(ND, 128);

    // ---------- layer 0 (F = 64) ----------
    {
        constexpr int G = INF / 4;   // 16 threads per node
        int npb = 256 / G;
        k_agg_mean<INF><<<cdiv(NG, npb), 256>>>(xg, rp_gg, col_gg, mgg, NG);
        k_agg_mean<INF><<<cdiv(NG, npb), 256>>>(xd, rp_dg, col_dg, mdg, NG);
        k_agg_mean<INF><<<cdiv(ND, npb), 256>>>(xg, rp_gd, col_gd, mgd, ND);
    }
    {
        GemmProb pg, pd;
        pg.A[0] = mgg; pg.A[1] = mdg; pg.A[2] = xg;
        pg.W[0] = Wn0; pg.W[1] = Wn0 + 2 * INF * HIDF; pg.W[2] = Wself0;
        pg.bias = bsum0; pg.C = hgA; pg.M = NG; pg.K = INF; pg.npan = 3;
        pd.A[0] = mgd; pd.A[1] = xd; pd.A[2] = nullptr;
        pd.W[0] = Wn0 + INF * HIDF; pd.W[1] = Ws0 + INF * HIDF; pd.W[2] = nullptr;
        pd.bias = b0 + HIDF; pd.C = hdA; pd.M = ND; pd.K = INF; pd.npan = 2;
        k_gemm_dual<HIDF, 8><<<nbG + nbD, 256>>>(pg, pd, nbG);
    }
    bn(hgA, NG, bng + 0 * HIDF, bnb + 0 * HIDF);
    bn(hdA, ND, bng + 1 * HIDF, bnb + 1 * HIDF);

    // ---------- layer 1 (F = 128) ----------
    {
        constexpr int G = HIDF / 4;  // 32 threads per node
        int npb = 256 / G;
        k_agg_mean<HIDF><<<cdiv(NG, npb), 256>>>(hgA, rp_gg, col_gg, mgg, NG);
        k_agg_mean<HIDF><<<cdiv(NG, npb), 256>>>(hdA, rp_dg, col_dg, mdg, NG);
        k_agg_mean<HIDF><<<cdiv(ND, npb), 256>>>(hgA, rp_gd, col_gd, mgd, ND);
    }
    {
        GemmProb pg, pd;
        pg.A[0] = mgg; pg.A[1] = mdg; pg.A[2] = hgA;
        pg.W[0] = Wn1; pg.W[1] = Wn1 + 2 * HIDF * HIDF; pg.W[2] = Wself1;
        pg.bias = bsum1; pg.C = hgB; pg.M = NG; pg.K = HIDF; pg.npan = 3;
        pd.A[0] = mgd; pd.A[1] = hdA; pd.A[2] = nullptr;
        pd.W[0] = Wn1 + HIDF * HIDF; pd.W[1] = Ws1 + HIDF * HIDF; pd.W[2] = nullptr;
        pd.bias = b1 + HIDF; pd.C = hdB; pd.M = ND; pd.K = HIDF; pd.npan = 2;
        k_gemm_dual<HIDF, 8><<<nbG + nbD, 256>>>(pg, pd, nbG);
    }
    bn(hgB, NG, bng + 2 * HIDF, bnb + 2 * HIDF);
    bn(hdB, ND, bng + 3 * HIDF, bnb + 3 * HIDF);

    // ---------- final projection (N = 64), both types in one launch ----------
    {
        GemmProb pg, pd;
        pg.A[0] = hgB; pg.A[1] = nullptr; pg.A[2] = nullptr;
        pg.W[0] = Wpm; pg.W[1] = nullptr; pg.W[2] = nullptr;
        pg.bias = bp; pg.C = out; pg.M = NG; pg.K = HIDF; pg.npan = 1;
        pd.A[0] = hdB; pd.A[1] = nullptr; pd.A[2] = nullptr;
        pd.W[0] = Wpm + HIDF * INF; pd.W[1] = nullptr; pd.W[2] = nullptr;
        pd.bias = bp + INF; pd.C = out + (long)NG * INF; pd.M = ND; pd.K = HIDF; pd.npan = 1;
        k_gemm_dual<INF, 4><<<nbG + nbD, 256>>>(pg, pd, nbG);
    }
}

// round 3
// speedup vs baseline: 1.7780x; 1.4147x over previous
#include <cuda_runtime.h>

#define NGn 50000
#define NDn 10000
#define INF 64
#define HIDF 128
#define E_GG 800000
#define E_GD 300000
#define E_DG 300000

// ---------------- static scratch ----------------
// cnt/pos segments: [0,NG) gg, [NG,2NG) dg, [2NG,2NG+ND) gd
__device__ int g_cnt[2 * NGn + NDn];
__device__ int g_pos[2 * NGn + NDn];
// rp segments: [0, NG+1) gg, [NG+1, 2NG+2) dg, [2NG+2, ...) gd
__device__ int g_rp[2 * NGn + NDn + 3];
__device__ int g_col_gg[E_GG];
__device__ int g_col_dg[E_DG];
__device__ int g_col_gd[E_GD];
__device__ int g_part[256];

__device__ float g_mgg[NGn * HIDF];
__device__ float g_mdg[NGn * HIDF];
__device__ float g_mgd[NDn * HIDF];
__device__ float g_hgA[NGn * HIDF];
__device__ float g_hdA[NDn * HIDF];
__device__ float g_hgB[NGn * HIDF];
__device__ float g_hdB[NDn * HIDF];

__device__ float g_Wself0[INF * HIDF];
__device__ float g_Wself1[HIDF * HIDF];
__device__ float g_bsum0[HIDF];
__device__ float g_bsum1[HIDF];
// stats: per layer [sumG(128), sqG(128), sumD(128), sqD(128)]
__device__ float g_stat[2 * 512];
__device__ float g_scale[2 * HIDF];
__device__ float g_shift[2 * HIDF];

// ---------------- f32x2 packed math helpers ----------------
__device__ __forceinline__ unsigned long long fma2(unsigned long long a,
                                                   unsigned long long b,
                                                   unsigned long long c) {
    unsigned long long d;
    asm("fma.rn.f32x2 %0, %1, %2, %3;" : "=l"(d) : "l"(a), "l"(b), "l"(c));
    return d;
}
__device__ __forceinline__ unsigned long long pack_dup(float x) {
    unsigned long long d;
    int xi = __float_as_int(x);
    asm("mov.b64 %0, {%1, %2};" : "=l"(d) : "r"(xi), "r"(xi));
    return d;
}
__device__ __forceinline__ float2 u2f2(unsigned long long u) {
    float2 f;
    asm("mov.b64 {%0, %1}, %2;" : "=f"(f.x), "=f"(f.y) : "l"(u));
    return f;
}

// ---------------- prep: fused weight/bias sums ----------------
__global__ void k_prep(const float* __restrict__ Ws0, const float* __restrict__ Ws1,
                       const float* __restrict__ b0, const float* __restrict__ b1,
                       float* __restrict__ Wself0, float* __restrict__ Wself1,
                       float* __restrict__ bsum0, float* __restrict__ bsum1) {
    int i = blockIdx.x * blockDim.x + threadIdx.x;
    if (i < INF * HIDF) Wself0[i] = Ws0[i] + Ws0[2 * INF * HIDF + i];
    if (i < HIDF * HIDF) Wself1[i] = Ws1[i] + Ws1[2 * HIDF * HIDF + i];
    if (i < HIDF) {
        bsum0[i] = b0[i] + b0[2 * HIDF + i];
        bsum1[i] = b1[i] + b1[2 * HIDF + i];
    }
}

// ---------------- fused 3-relation CSR build ----------------
__global__ void k_hist3(const int* __restrict__ d0, const int* __restrict__ d1,
                        const int* __restrict__ d2, int e0, int e1, int e2,
                        int n0, int n1, int* __restrict__ cnt) {
    int i = blockIdx.x * blockDim.x + threadIdx.x;
    if (i < e0) atomicAdd(&cnt[d0[i]], 1);
    else if (i < e0 + e1) atomicAdd(&cnt[n0 + d1[i - e0]], 1);
    else if (i < e0 + e1 + e2) atomicAdd(&cnt[n0 + n1 + d2[i - e0 - e1]], 1);
}

// pass 1: per-1024-chunk sums, segmented
__global__ void k_scan_part3(const int* __restrict__ cnt, int n0, int n1, int n2,
                             int nb0, int nb1, int* __restrict__ part) {
    __shared__ int s[1024];
    int b = blockIdx.x;
    int base, n, lb;
    if (b < nb0) { base = 0; n = n0; lb = b; }
    else if (b < nb0 + nb1) { base = n0; n = n1; lb = b - nb0; }
    else { base = n0 + n1; n = n2; lb = b - nb0 - nb1; }
    int i = lb * 1024 + threadIdx.x;
    int v = (i < n) ? cnt[base + i] : 0;
    s[threadIdx.x] = v;
    __syncthreads();
    for (int off = 512; off > 0; off >>= 1) {
        if (threadIdx.x < off) s[threadIdx.x] += s[threadIdx.x + off];
        __syncthreads();
    }
    if (threadIdx.x == 0) part[b] = s[0];
}

// pass 2: exclusive scan of partials per segment (3 blocks), write rp[n]=total
__global__ void k_scan_mid3(int* __restrict__ part, int nb0, int nb1, int nb2,
                            int n0, int n1, int n2, int* __restrict__ rp) {
    __shared__ int s[64];
    int seg = blockIdx.x;
    int pbase = (seg == 0) ? 0 : (seg == 1) ? nb0 : nb0 + nb1;
    int nb = (seg == 0) ? nb0 : (seg == 1) ? nb1 : nb2;
    int rbase = (seg == 0) ? 0 : (seg == 1) ? (n0 + 1) : (n0 + n1 + 2);
    int n = (seg == 0) ? n0 : (seg == 1) ? n1 : n2;
    int v = (threadIdx.x < nb) ? part[pbase + threadIdx.x] : 0;
    s[threadIdx.x] = v;
    __syncthreads();
    for (int off = 1; off < 64; off <<= 1) {
        int t = (threadIdx.x >= off) ? s[threadIdx.x - off] : 0;
        __syncthreads();
        s[threadIdx.x] += t;
        __syncthreads();
    }
    if (threadIdx.x < nb) part[pbase + threadIdx.x] = s[threadIdx.x] - v;
    if (threadIdx.x == 63) rp[rbase + n] = s[63];
}

// pass 3: per-chunk inclusive scan + offset -> exclusive rp; also writes pos
__global__ void k_scan_final3(const int* __restrict__ cnt, int n0, int n1, int n2,
                              int nb0, int nb1, const int* __restrict__ part,
                              int* __restrict__ rp, int* __restrict__ pos) {
    __shared__ int s[1024];
    int b = blockIdx.x;
    int cbase, rbase, n, lb;
    if (b < nb0) { cbase = 0; rbase = 0; n = n0; lb = b; }
    else if (b < nb0 + nb1) { cbase = n0; rbase = n0 + 1; n = n1; lb = b - nb0; }
    else { cbase = n0 + n1; rbase = n0 + n1 + 2; n = n2; lb = b - nb0 - nb1; }
    int i = lb * 1024 + threadIdx.x;
    int v = (i < n) ? cnt[cbase + i] : 0;
    s[threadIdx.x] = v;
    __syncthreads();
    for (int off = 1; off < 1024; off <<= 1) {
        int t = (threadIdx.x >= off) ? s[threadIdx.x - off] : 0;
        __syncthreads();
        s[threadIdx.x] += t;
        __syncthreads();
    }
    if (i < n) {
        int ex = part[b] + s[threadIdx.x] - v;
        rp[rbase + i] = ex;
        pos[cbase + i] = ex;
    }
}

__global__ void k_scatter3(const int* __restrict__ s0, const int* __restrict__ d0,
                           const int* __restrict__ s1, const int* __restrict__ d1,
                           const int* __restrict__ s2, const int* __restrict__ d2,
                           int e0, int e1, int e2, int n0, int n1,
                           int* __restrict__ pos, int* __restrict__ c0,
                           int* __restrict__ c1, int* __restrict__ c2) {
    int i = blockIdx.x * blockDim.x + threadIdx.x;
    if (i < e0) {
        int p = atomicAdd(&pos[d0[i]], 1);
        c0[p] = s0[i];
    } else if (i < e0 + e1) {
        int j = i - e0;
        int p = atomicAdd(&pos[n0 + d1[j]], 1);
        c1[p] = s1[j];
    } else if (i < e0 + e1 + e2) {
        int j = i - e0 - e1;
        int p = atomicAdd(&pos[n0 + n1 + d2[j]], 1);
        c2[p] = s2[j];
    }
}

// ---------------- fused 3-relation mean aggregation ----------------
struct AggRel {
    const float* hsrc;
    const int* rp;
    const int* col;
    float* out;
    int ndst;
};

template <int F>
__global__ void k_agg3(AggRel ra, AggRel rb, AggRel rc, int nb0, int nb01) {
    constexpr int G = F / 4;
    int gpb = 256 / G;
    AggRel R;
    int lb;
    if (blockIdx.x < nb0) { R = ra; lb = blockIdx.x; }
    else if (blockIdx.x < nb01) { R = rb; lb = blockIdx.x - nb0; }
    else { R = rc; lb = blockIdx.x - nb01; }
    int node = lb * gpb + (threadIdx.x / G);
    int lane = threadIdx.x % G;
    if (node >= R.ndst) return;
    int s = R.rp[node];
    int e = R.rp[node + 1];
    float4 acc0 = make_float4(0.f, 0.f, 0.f, 0.f);
    float4 acc1 = make_float4(0.f, 0.f, 0.f, 0.f);
    int i = s;
    for (; i + 1 < e; i += 2) {
        int i0 = __ldg(&R.col[i]);
        int i1 = __ldg(&R.col[i + 1]);
        float4 v0 = __ldg((const float4*)&R.hsrc[(long)i0 * F + lane * 4]);
        float4 v1 = __ldg((const float4*)&R.hsrc[(long)i1 * F + lane * 4]);
        acc0.x += v0.x; acc0.y += v0.y; acc0.z += v0.z; acc0.w += v0.w;
        acc1.x += v1.x; acc1.y += v1.y; acc1.z += v1.z; acc1.w += v1.w;
    }
    if (i < e) {
        int i0 = __ldg(&R.col[i]);
        float4 v0 = __ldg((const float4*)&R.hsrc[(long)i0 * F + lane * 4]);
        acc0.x += v0.x; acc0.y += v0.y; acc0.z += v0.z; acc0.w += v0.w;
    }
    acc0.x += acc1.x; acc0.y += acc1.y; acc0.z += acc1.z; acc0.w += acc1.w;
    float inv = (e > s) ? 1.f / (float)(e - s) : 0.f;
    acc0.x *= inv; acc0.y *= inv; acc0.z *= inv; acc0.w *= inv;
    ((float4*)&R.out[(long)node * F])[lane] = acc0;
}

// ---------------- dual-problem multi-panel SGEMM (f32x2 core) ----------------
struct GemmProb {
    const float* A[3];
    const float* W[3];
    const float* bias;
    float* C;
    float* statS;  // optional column-sum accumulator (nullptr to skip)
    float* statQ;  // optional column-sumsq accumulator
    int M, K, npan;
};

// BM=128, BK=16, TM=8, 256 threads. Double-buffered smem + register prefetch.
template <int BN, int TN>
__global__ void __launch_bounds__(256, 2)
k_gemm_dual(GemmProb pa, GemmProb pb, int nb0) {
    constexpr int BM = 128;
    constexpr int BK = 16;
    constexpr int TM = 8;
    constexpr int LDA = BM + 4;
    constexpr int NW = (BK * BN / 4) / 256;  // W float4 loads per thread
    constexpr int TNP = TN / 2;
    __shared__ float As[2][BK][LDA];
    __shared__ float Ws[2][BK][BN];

    bool second = (blockIdx.x >= nb0);
    GemmProb P = second ? pb : pa;
    int bid = second ? (blockIdx.x - nb0) : blockIdx.x;
    int rowBase = bid * BM;
    int tid = threadIdx.x;
    int tx = tid % (BN / TN);
    int ty = tid / (BN / TN);

    int ktiles = P.K / BK;
    int T = P.npan * ktiles;

    unsigned long long accP[TM][TNP];
#pragma unroll
    for (int i = 0; i < TM; i++)
#pragma unroll
        for (int j = 0; j < TNP; j++) accP[i][j] = 0ULL;

    float4 rA[2];
    float4 rW[NW];

    int ar[2], ac4[2];
#pragma unroll
    for (int it = 0; it < 2; it++) {
        int f = tid + it * 256;
        ar[it] = f >> 2;
        ac4[it] = f & 3;
    }

    auto ldgTile = [&](int t) {
        int p = t / ktiles;
        int kt = (t - p * ktiles) * BK;
        const float* A = P.A[p];
        const float* W = P.W[p];
#pragma unroll
        for (int it = 0; it < 2; it++) {
            int row = rowBase + ar[it];
            if (row >= P.M) row = P.M - 1;  // clamp; OOB rows never written
            rA[it] = *(const float4*)&A[(long)row * P.K + kt + ac4[it] * 4];
        }
#pragma unroll
        for (int it = 0; it < NW; it++) {
            int f = tid + it * 256;
            int r = f / (BN / 4);
            int c4 = f % (BN / 4);
            rW[it] = *(const float4*)&W[(long)(kt + r) * BN + c4 * 4];
        }
    };

    ldgTile(0);
    for (int t = 0; t < T; t++) {
        int sbuf = t & 1;
#pragma unroll
        for (int it = 0; it < 2; it++) {
            As[sbuf][ac4[it] * 4 + 0][ar[it]] = rA[it].x;
            As[sbuf][ac4[it] * 4 + 1][ar[it]] = rA[it].y;
            As[sbuf][ac4[it] * 4 + 2][ar[it]] = rA[it].z;
            As[sbuf][ac4[it] * 4 + 3][ar[it]] = rA[it].w;
        }
#pragma unroll
        for (int it = 0; it < NW; it++) {
            int f = tid + it * 256;
            int r = f / (BN / 4);
            int c4 = f % (BN / 4);
            *(float4*)&Ws[sbuf][r][c4 * 4] = rW[it];
        }
        if (t + 1 < T) ldgTile(t + 1);
        __syncthreads();
#pragma unroll
        for (int kk = 0; kk < BK; kk++) {
            float ra[TM];
#pragma unroll
            for (int i = 0; i < TM; i += 4)
                *(float4*)&ra[i] = *(const float4*)&As[sbuf][kk][ty * TM + i];
            unsigned long long rbp[TNP];
#pragma unroll
            for (int q = 0; q < TN / 4; q++) {
                ulonglong2 w = *(const ulonglong2*)&Ws[sbuf][kk][tx * TN + q * 4];
                rbp[2 * q] = w.x;
                rbp[2 * q + 1] = w.y;
            }
#pragma unroll
            for (int i = 0; i < TM; i++) {
                unsigned long long ad = pack_dup(ra[i]);
#pragma unroll
                for (int j = 0; j < TNP; j++) accP[i][j] = fma2(ad, rbp[j], accP[i][j]);
            }
        }
        __syncthreads();
    }

    // ---- epilogue: bias, optional BN stats, write ----
    float bcol[TN];
#pragma unroll
    for (int q = 0; q < TN / 4; q++)
        *(float4*)&bcol[q * 4] = *(const float4*)&P.bias[tx * TN + q * 4];

    float vv[TM][TN];
#pragma unroll
    for (int i = 0; i < TM; i++)
#pragma unroll
        for (int j = 0; j < TNP; j++) {
            float2 f = u2f2(accP[i][j]);
            vv[i][2 * j] = f.x + bcol[2 * j];
            vv[i][2 * j + 1] = f.y + bcol[2 * j + 1];
        }

    bool valid[TM];
#pragma unroll
    for (int i = 0; i < TM; i++) valid[i] = (rowBase + ty * TM + i) < P.M;

    if (P.statS) {
        float* sm = &As[0][0][0];  // 4224 floats scratch; need 16*BN <= 2048
#pragma unroll
        for (int j = 0; j < TN; j++) {
            float s = 0.f;
#pragma unroll
            for (int i = 0; i < TM; i++)
                if (valid[i]) s += vv[i][j];
            sm[ty * BN + tx * TN + j] = s;
        }
        __syncthreads();
        if (tid < BN) {
            float t = 0.f;
#pragma unroll
            for (int r = 0; r < 16; r++) t += sm[r * BN + tid];
            atomicAdd(&P.statS[tid], t);
        }
        __syncthreads();
#pragma unroll
        for (int j = 0; j < TN; j++) {
            float s = 0.f;
#pragma unroll
            for (int i = 0; i < TM; i++)
                if (valid[i]) s = fmaf(vv[i][j], vv[i][j], s);
            sm[ty * BN + tx * TN + j] = s;
        }
        __syncthreads();
        if (tid < BN) {
            float t = 0.f;
#pragma unroll
            for (int r = 0; r < 16; r++) t += sm[r * BN + tid];
            atomicAdd(&P.statQ[tid], t);
        }
    }

#pragma unroll
    for (int i = 0; i < TM; i++) {
        if (!valid[i]) continue;
        int row = rowBase + ty * TM + i;
#pragma unroll
        for (int q = 0; q < TN / 4; q++)
            *(float4*)&P.C[(long)row * BN + tx * TN + q * 4] = *(float4*)&vv[i][q * 4];
    }
}

// ---------------- BatchNorm (both types in one launch) ----------------
__global__ void k_bn_fin2(const float* __restrict__ stat, float Mg, float Md,
                          const float* __restrict__ g, const float* __restrict__ b,
                          float* __restrict__ scale2, float* __restrict__ shift2) {
    int tid = threadIdx.x;  // 256
    int t = tid >> 7, c = tid & 127;
    float Mf = t ? Md : Mg;
    float sum = stat[t * 256 + c];
    float sq = stat[t * 256 + 128 + c];
    float mu = sum / Mf;
    float var = sq / Mf - mu * mu;
    float sc = g[t * 128 + c] * rsqrtf(var + 1e-5f);
    scale2[t * 128 + c] = sc;
    shift2[t * 128 + c] = b[t * 128 + c] - mu * sc;
}

__global__ void k_bn_relu2(float* __restrict__ Xg, float* __restrict__ Xd,
                           int nG4, int nD4, const float* __restrict__ scale2,
                           const float* __restrict__ shift2) {
    int i = blockIdx.x * blockDim.x + threadIdx.x;
    float* X;
    int li, t;
    if (i < nG4) { X = Xg; li = i; t = 0; }
    else if (i < nG4 + nD4) { X = Xd; li = i - nG4; t = 1; }
    else return;
    float4 v = ((float4*)X)[li];
    int c = t * 128 + (li & 31) * 4;
    v.x = fmaxf(0.f, fmaf(v.x, __ldg(&scale2[c + 0]), __ldg(&shift2[c + 0])));
    v.y = fmaxf(0.f, fmaf(v.y, __ldg(&scale2[c + 1]), __ldg(&shift2[c + 1])));
    v.z = fmaxf(0.f, fmaf(v.z, __ldg(&scale2[c + 2]), __ldg(&shift2[c + 2])));
    v.w = fmaxf(0.f, fmaf(v.w, __ldg(&scale2[c + 3]), __ldg(&shift2[c + 3])));
    ((float4*)X)[li] = v;
}

// ---------------- host side ----------------
template <typename T>
static T* sym(const void* s) {
    void* p = nullptr;
    cudaGetSymbolAddress(&p, s);
    return (T*)p;
}

extern "C" void kernel_launch(void* const* d_in, const int* in_sizes, int n_in,
                              void* d_out, int out_size) {
    const float* xg  = (const float*)d_in[0];
    const float* xd  = (const float*)d_in[1];
    const float* Wn0 = (const float*)d_in[2];
    const float* Ws0 = (const float*)d_in[3];
    const float* b0  = (const float*)d_in[4];
    const float* Wn1 = (const float*)d_in[5];
    const float* Ws1 = (const float*)d_in[6];
    const float* b1  = (const float*)d_in[7];
    const float* bng = (const float*)d_in[8];
    const float* bnb = (const float*)d_in[9];
    const float* Wpm = (const float*)d_in[10];
    const float* bp  = (const float*)d_in[11];
    const int* gg_src = (const int*)d_in[12];
    const int* gg_dst = (const int*)d_in[13];
    const int* gd_src = (const int*)d_in[14];
    const int* gd_dst = (const int*)d_in[15];
    const int* dg_src = (const int*)d_in[16];
    const int* dg_dst = (const int*)d_in[17];

    const int NG = in_sizes[0] / INF;
    const int ND = in_sizes[1] / INF;
    const int egg = in_sizes[12];
    const int egd = in_sizes[14];
    const int edg = in_sizes[16];

    float* out = (float*)d_out;

    int* cnt = sym<int>(g_cnt);
    int* pos = sym<int>(g_pos);
    int* rp = sym<int>(g_rp);
    int* col_gg = sym<int>(g_col_gg);
    int* col_dg = sym<int>(g_col_dg);
    int* col_gd = sym<int>(g_col_gd);
    int* part = sym<int>(g_part);
    float* mgg = sym<float>(g_mgg);
    float* mdg = sym<float>(g_mdg);
    float* mgd = sym<float>(g_mgd);
    float* hgA = sym<float>(g_hgA);
    float* hdA = sym<float>(g_hdA);
    float* hgB = sym<float>(g_hgB);
    float* hdB = sym<float>(g_hdB);
    float* Wself0 = sym<float>(g_Wself0);
    float* Wself1 = sym<float>(g_Wself1);
    float* bsum0 = sym<float>(g_bsum0);
    float* bsum1 = sym<float>(g_bsum1);
    float* stat = sym<float>(g_stat);
    float* scale = sym<float>(g_scale);
    float* shift = sym<float>(g_shift);

    auto cdiv = [](int a, int b) { return (a + b - 1) / b; };

    // rp segment bases
    int* rp_gg = rp;
    int* rp_dg = rp + NG + 1;
    int* rp_gd = rp + 2 * NG + 2;

    // --- zero counters and BN stats ---
    cudaMemsetAsync(cnt, 0, (2 * NG + ND) * sizeof(int));
    cudaMemsetAsync(stat, 0, 2 * 512 * sizeof(float));

    // --- fused 3-relation CSR build (by destination) ---
    int etot = egg + edg + egd;
    k_hist3<<<cdiv(etot, 256), 256>>>(gg_dst, dg_dst, gd_dst, egg, edg, egd, NG, NG, cnt);
    int nb0 = cdiv(NG, 1024), nb1 = cdiv(NG, 1024), nb2 = cdiv(ND, 1024);
    k_scan_part3<<<nb0 + nb1 + nb2, 1024>>>(cnt, NG, NG, ND, nb0, nb1, part);
    k_scan_mid3<<<3, 64>>>(part, nb0, nb1, nb2, NG, NG, ND, rp);
    k_scan_final3<<<nb0 + nb1 + nb2, 1024>>>(cnt, NG, NG, ND, nb0, nb1, part, rp, pos);
    k_scatter3<<<cdiv(etot, 256), 256>>>(gg_src, gg_dst, dg_src, dg_dst, gd_src, gd_dst,
                                         egg, edg, egd, NG, NG, pos, col_gg, col_dg, col_gd);

    int nbG = cdiv(NG, 128);
    int nbD = cdiv(ND, 128);

    // ---------- layer 0 aggregation (F = 64): 3 relations, one launch ----------
    {
        constexpr int gpb = 256 / (INF / 4);  // 16 nodes per block
        AggRel a{xg, rp_gg, col_gg, mgg, NG};
        AggRel b{xd, rp_dg, col_dg, mdg, NG};
        AggRel c{xg, rp_gd, col_gd, mgd, ND};
        int na = cdiv(NG, gpb), nbk = cdiv(NG, gpb), nc = cdiv(ND, gpb);
        k_agg3<INF><<<na + nbk + nc, 256>>>(a, b, c, na, na + nbk);
    }

    k_prep<<<cdiv(HIDF * HIDF, 256), 256>>>(Ws0, Ws1, b0, b1, Wself0, Wself1, bsum0, bsum1);

    // ---------- layer 0 GEMM + fused BN stats ----------
    {
        GemmProb pg, pd;
        pg.A[0] = mgg; pg.A[1] = mdg; pg.A[2] = xg;
        pg.W[0] = Wn0; pg.W[1] = Wn0 + 2 * INF * HIDF; pg.W[2] = Wself0;
        pg.bias = bsum0; pg.C = hgA; pg.M = NG; pg.K = INF; pg.npan = 3;
        pg.statS = stat; pg.statQ = stat + 128;
        pd.A[0] = mgd; pd.A[1] = xd; pd.A[2] = nullptr;
        pd.W[0] = Wn0 + INF * HIDF; pd.W[1] = Ws0 + INF * HIDF; pd.W[2] = nullptr;
        pd.bias = b0 + HIDF; pd.C = hdA; pd.M = ND; pd.K = INF; pd.npan = 2;
        pd.statS = stat + 256; pd.statQ = stat + 384;
        k_gemm_dual<HIDF, 8><<<nbG + nbD, 256>>>(pg, pd, nbG);
    }
    k_bn_fin2<<<1, 256>>>(stat, (float)NG, (float)ND, bng, bnb, scale, shift);
    {
        int nG4 = NG * HIDF / 4, nD4 = ND * HIDF / 4;
        k_bn_relu2<<<cdiv(nG4 + nD4, 256), 256>>>(hgA, hdA, nG4, nD4, scale, shift);
    }

    // ---------- layer 1 aggregation (F = 128) ----------
    {
        constexpr int gpb = 256 / (HIDF / 4);  // 8 nodes per block
        AggRel a{hgA, rp_gg, col_gg, mgg, NG};
        AggRel b{hdA, rp_dg, col_dg, mdg, NG};
        AggRel c{hgA, rp_gd, col_gd, mgd, ND};
        int na = cdiv(NG, gpb), nbk = cdiv(NG, gpb), nc = cdiv(ND, gpb);
        k_agg3<HIDF><<<na + nbk + nc, 256>>>(a, b, c, na, na + nbk);
    }

    // ---------- layer 1 GEMM + fused BN stats ----------
    {
        GemmProb pg, pd;
        pg.A[0] = mgg; pg.A[1] = mdg; pg.A[2] = hgA;
        pg.W[0] = Wn1; pg.W[1] = Wn1 + 2 * HIDF * HIDF; pg.W[2] = Wself1;
        pg.bias = bsum1; pg.C = hgB; pg.M = NG; pg.K = HIDF; pg.npan = 3;
        pg.statS = stat + 512; pg.statQ = stat + 640;
        pd.A[0] = mgd; pd.A[1] = hdA; pd.A[2] = nullptr;
        pd.W[0] = Wn1 + HIDF * HIDF; pd.W[1] = Ws1 + HIDF * HIDF; pd.W[2] = nullptr;
        pd.bias = b1 + HIDF; pd.C = hdB; pd.M = ND; pd.K = HIDF; pd.npan = 2;
        pd.statS = stat + 768; pd.statQ = stat + 896;
        k_gemm_dual<HIDF, 8><<<nbG + nbD, 256>>>(pg, pd, nbG);
    }
    k_bn_fin2<<<1, 256>>>(stat + 512, (float)NG, (float)ND, bng + 256, bnb + 256, scale, shift);
    {
        int nG4 = NG * HIDF / 4, nD4 = ND * HIDF / 4;
        k_bn_relu2<<<cdiv(nG4 + nD4, 256), 256>>>(hgB, hdB, nG4, nD4, scale, shift);
    }

    // ---------- final projection (N = 64), both types in one launch ----------
    {
        GemmProb pg, pd;
        pg.A[0] = hgB; pg.A[1] = nullptr; pg.A[2] = nullptr;
        pg.W[0] = Wpm; pg.W[1] = nullptr; pg.W[2] = nullptr;
        pg.bias = bp; pg.C = out; pg.M = NG; pg.K = HIDF; pg.npan = 1;
        pg.statS = nullptr; pg.statQ = nullptr;
        pd.A[0] = hdB; pd.A[1] = nullptr; pd.A[2] = nullptr;
        pd.W[0] = Wpm + HIDF * INF; pd.W[1] = nullptr; pd.W[2] = nullptr;
        pd.bias = bp + INF; pd.C = out + (long)NG * INF; pd.M = ND; pd.K = HIDF; pd.npan = 1;
        pd.statS = nullptr; pd.statQ = nullptr;
        k_gemm_dual<INF, 4><<<nbG + nbD, 256>>>(pg, pd, nbG);
    }
}

// round 5
// speedup vs baseline: 2.0842x; 1.1722x over previous
#include <cuda_runtime.h>
#include <cstdint>

#define NGn 50000
#define NDn 10000
#define INF 64
#define HIDF 128
#define E_GG 800000
#define E_GD 300000
#define E_DG 300000

// ---------------- static scratch ----------------
__device__ int g_cnt[2 * NGn + NDn];
__device__ int g_pos[2 * NGn + NDn];
__device__ int g_rp[2 * NGn + NDn + 3];
__device__ int g_col_gg[E_GG];
__device__ int g_col_dg[E_DG];
__device__ int g_col_gd[E_GD];
__device__ int g_part[256];

__device__ float g_mgg[NGn * HIDF];
__device__ float g_mdg[NGn * HIDF];
__device__ float g_mgd[NDn * HIDF];
__device__ float g_hgA[NGn * HIDF];
__device__ float g_hdA[NDn * HIDF];
__device__ float g_hgB[NGn * HIDF];
__device__ float g_hdB[NDn * HIDF];

__device__ float g_Wself0[INF * HIDF];
__device__ float g_Wself1[HIDF * HIDF];
__device__ float g_bsum0[HIDF];
__device__ float g_bsum1[HIDF];
__device__ float g_stat[2 * 512];
__device__ float g_scale[2 * HIDF];
__device__ float g_shift[2 * HIDF];

// exact bf16 hi/lo split, packed bf16x2 (low half = first element)
__device__ __forceinline__ void split2(float a0, float a1, uint32_t& hi, uint32_t& lo) {
    uint32_t b0 = __float_as_uint(a0), b1 = __float_as_uint(a1);
    uint32_t h0 = b0 & 0xFFFF0000u, h1 = b1 & 0xFFFF0000u;
    float l0 = a0 - __uint_as_float(h0);
    float l1 = a1 - __uint_as_float(h1);
    uint32_t c0 = __float_as_uint(l0), c1 = __float_as_uint(l1);
    hi = h1 | (h0 >> 16);
    lo = (c1 & 0xFFFF0000u) | (c0 >> 16);
}

#define MMA_BF16(d, a, b)                                                       \
    asm volatile(                                                               \
        "mma.sync.aligned.m16n8k16.row.col.f32.bf16.bf16.f32 "                  \
        "{%0,%1,%2,%3},{%4,%5,%6,%7},{%8,%9},{%0,%1,%2,%3};"                    \
        : "+f"((d)[0]), "+f"((d)[1]), "+f"((d)[2]), "+f"((d)[3])                \
        : "r"((a)[0]), "r"((a)[1]), "r"((a)[2]), "r"((a)[3]),                   \
          "r"((b)[0]), "r"((b)[1]))

// ---------------- prep: zero counters/stats + fused weight/bias sums --------
__global__ void k_prep(const float* __restrict__ Ws0, const float* __restrict__ Ws1,
                       const float* __restrict__ b0, const float* __restrict__ b1,
                       float* __restrict__ Wself0, float* __restrict__ Wself1,
                       float* __restrict__ bsum0, float* __restrict__ bsum1,
                       int* __restrict__ cnt, int ncnt, float* __restrict__ stat) {
    int i = blockIdx.x * blockDim.x + threadIdx.x;
    if (i < ncnt) cnt[i] = 0;
    if (i < 1024) stat[i] = 0.f;
    if (i < INF * HIDF) Wself0[i] = Ws0[i] + Ws0[2 * INF * HIDF + i];
    if (i < HIDF * HIDF) Wself1[i] = Ws1[i] + Ws1[2 * HIDF * HIDF + i];
    if (i < HIDF) {
        bsum0[i] = b0[i] + b0[2 * HIDF + i];
        bsum1[i] = b1[i] + b1[2 * HIDF + i];
    }
}

// ---------------- fused 3-relation CSR build ----------------
__global__ void k_hist3(const int* __restrict__ d0, const int* __restrict__ d1,
                        const int* __restrict__ d2, int e0, int e1, int e2,
                        int n0, int n1, int* __restrict__ cnt) {
    int i = blockIdx.x * blockDim.x + threadIdx.x;
    if (i < e0) atomicAdd(&cnt[d0[i]], 1);
    else if (i < e0 + e1) atomicAdd(&cnt[n0 + d1[i - e0]], 1);
    else if (i < e0 + e1 + e2) atomicAdd(&cnt[n0 + n1 + d2[i - e0 - e1]], 1);
}

__global__ void k_scan_part3(const int* __restrict__ cnt, int n0, int n1, int n2,
                             int nb0, int nb1, int* __restrict__ part) {
    __shared__ int s[1024];
    int b = blockIdx.x;
    int base, n, lb;
    if (b < nb0) { base = 0; n = n0; lb = b; }
    else if (b < nb0 + nb1) { base = n0; n = n1; lb = b - nb0; }
    else { base = n0 + n1; n = n2; lb = b - nb0 - nb1; }
    int i = lb * 1024 + threadIdx.x;
    int v = (i < n) ? cnt[base + i] : 0;
    s[threadIdx.x] = v;
    __syncthreads();
    for (int off = 512; off > 0; off >>= 1) {
        if (threadIdx.x < off) s[threadIdx.x] += s[threadIdx.x + off];
        __syncthreads();
    }
    if (threadIdx.x == 0) part[b] = s[0];
}

__global__ void k_scan_mid3(int* __restrict__ part, int nb0, int nb1, int nb2,
                            int n0, int n1, int n2, int* __restrict__ rp) {
    __shared__ int s[64];
    int seg = blockIdx.x;
    int pbase = (seg == 0) ? 0 : (seg == 1) ? nb0 : nb0 + nb1;
    int nb = (seg == 0) ? nb0 : (seg == 1) ? nb1 : nb2;
    int rbase = (seg == 0) ? 0 : (seg == 1) ? (n0 + 1) : (n0 + n1 + 2);
    int n = (seg == 0) ? n0 : (seg == 1) ? n1 : n2;
    int v = (threadIdx.x < nb) ? part[pbase + threadIdx.x] : 0;
    s[threadIdx.x] = v;
    __syncthreads();
    for (int off = 1; off < 64; off <<= 1) {
        int t = (threadIdx.x >= off) ? s[threadIdx.x - off] : 0;
        __syncthreads();
        s[threadIdx.x] += t;
        __syncthreads();
    }
    if (threadIdx.x < nb) part[pbase + threadIdx.x] = s[threadIdx.x] - v;
    if (threadIdx.x == 63) rp[rbase + n] = s[63];
}

__global__ void k_scan_final3(const int* __restrict__ cnt, int n0, int n1, int n2,
                              int nb0, int nb1, const int* __restrict__ part,
                              int* __restrict__ rp, int* __restrict__ pos) {
    __shared__ int s[1024];
    int b = blockIdx.x;
    int cbase, rbase, n, lb;
    if (b < nb0) { cbase = 0; rbase = 0; n = n0; lb = b; }
    else if (b < nb0 + nb1) { cbase = n0; rbase = n0 + 1; n = n1; lb = b - nb0; }
    else { cbase = n0 + n1; rbase = n0 + n1 + 2; n = n2; lb = b - nb0 - nb1; }
    int i = lb * 1024 + threadIdx.x;
    int v = (i < n) ? cnt[cbase + i] : 0;
    s[threadIdx.x] = v;
    __syncthreads();
    for (int off = 1; off < 1024; off <<= 1) {
        int t = (threadIdx.x >= off) ? s[threadIdx.x - off] : 0;
        __syncthreads();
        s[threadIdx.x] += t;
        __syncthreads();
    }
    if (i < n) {
        int ex = part[b] + s[threadIdx.x] - v;
        rp[rbase + i] = ex;
        pos[cbase + i] = ex;
    }
}

__global__ void k_scatter3(const int* __restrict__ s0, const int* __restrict__ d0,
                           const int* __restrict__ s1, const int* __restrict__ d1,
                           const int* __restrict__ s2, const int* __restrict__ d2,
                           int e0, int e1, int e2, int n0, int n1,
                           int* __restrict__ pos, int* __restrict__ c0,
                           int* __restrict__ c1, int* __restrict__ c2) {
    int i = blockIdx.x * blockDim.x + threadIdx.x;
    if (i < e0) {
        int p = atomicAdd(&pos[d0[i]], 1);
        c0[p] = s0[i];
    } else if (i < e0 + e1) {
        int j = i - e0;
        int p = atomicAdd(&pos[n0 + d1[j]], 1);
        c1[p] = s1[j];
    } else if (i < e0 + e1 + e2) {
        int j = i - e0 - e1;
        int p = atomicAdd(&pos[n0 + n1 + d2[j]], 1);
        c2[p] = s2[j];
    }
}

// ---------------- fused 3-relation mean aggregation ----------------
struct AggRel {
    const float* hsrc;
    const int* rp;
    const int* col;
    float* out;
    int ndst;
};

template <int F>
__global__ void k_agg3(AggRel ra, AggRel rb, AggRel rc, int nb0, int nb01) {
    constexpr int G = F / 4;
    int gpb = 256 / G;
    AggRel R;
    int lb;
    if (blockIdx.x < nb0) { R = ra; lb = blockIdx.x; }
    else if (blockIdx.x < nb01) { R = rb; lb = blockIdx.x - nb0; }
    else { R = rc; lb = blockIdx.x - nb01; }
    int node = lb * gpb + (threadIdx.x / G);
    int lane = threadIdx.x % G;
    if (node >= R.ndst) return;
    int s = R.rp[node];
    int e = R.rp[node + 1];
    float4 acc0 = make_float4(0.f, 0.f, 0.f, 0.f);
    float4 acc1 = make_float4(0.f, 0.f, 0.f, 0.f);
    int i = s;
    for (; i + 1 < e; i += 2) {
        int i0 = __ldg(&R.col[i]);
        int i1 = __ldg(&R.col[i + 1]);
        float4 v0 = __ldg((const float4*)&R.hsrc[(long)i0 * F + lane * 4]);
        float4 v1 = __ldg((const float4*)&R.hsrc[(long)i1 * F + lane * 4]);
        acc0.x += v0.x; acc0.y += v0.y; acc0.z += v0.z; acc0.w += v0.w;
        acc1.x += v1.x; acc1.y += v1.y; acc1.z += v1.z; acc1.w += v1.w;
    }
    if (i < e) {
        int i0 = __ldg(&R.col[i]);
        float4 v0 = __ldg((const float4*)&R.hsrc[(long)i0 * F + lane * 4]);
        acc0.x += v0.x; acc0.y += v0.y; acc0.z += v0.z; acc0.w += v0.w;
    }
    acc0.x += acc1.x; acc0.y += acc1.y; acc0.z += acc1.z; acc0.w += acc1.w;
    float inv = (e > s) ? 1.f / (float)(e - s) : 0.f;
    acc0.x *= inv; acc0.y *= inv; acc0.z *= inv; acc0.w *= inv;
    ((float4*)&R.out[(long)node * F])[lane] = acc0;
}

// ---------------- HMMA (mma.sync bf16 3-term split) dual-problem GEMM -------
// D[M,BN] = sum_p A_p[M,K] @ W_p[K,BN] + bias; fp32 I/O; ~3e-5 accuracy.
struct GemmProb {
    const float* A[3];
    const float* W[3];
    const float* bias;
    float* C;
    float* statS;
    float* statQ;
    int M, K, npan;
};

template <int BN>
__global__ void __launch_bounds__(256, 1)
k_gemm_mma(GemmProb pa, GemmProb pb, int nb0) {
    constexpr int WN = BN / 2;       // warp N tile (4 M-warps x 2 N-warps)
    constexpr int NS = WN / 8;       // n-steps per warp
    constexpr int LDK = 40;          // bf16 elems per row (32 + 8 pad)
    constexpr int APLANE = 128 * LDK;
    constexpr int BPLANE = BN * LDK;
    constexpr int BUFE = 2 * APLANE + 2 * BPLANE;  // bf16 elems per buffer
    constexpr int BS = (16 * (BN / 4)) / 256;      // B slots per thread (1 or 2)

    extern __shared__ __align__(16) uint16_t smb[];
    __shared__ float sS[128], sQ[128];

    int tid = threadIdx.x;
    int lane = tid & 31, wid = tid >> 5;
    int wm = wid & 3, wn = wid >> 2;
    int tq = lane >> 2, tr = lane & 3;

    bool second = (blockIdx.x >= nb0);
    GemmProb P = second ? pb : pa;
    int bid = second ? (blockIdx.x - nb0) : blockIdx.x;
    int rowBase = bid * 128;

    if (tid < 128) { sS[tid] = 0.f; sQ[tid] = 0.f; }

    const int K = P.K;
    const int ktiles = K >> 5;           // 32-wide K tiles per panel
    const int T = P.npan * ktiles;

    float acc[2][NS][4];
#pragma unroll
    for (int m = 0; m < 2; m++)
#pragma unroll
        for (int n = 0; n < NS; n++)
#pragma unroll
            for (int j = 0; j < 4; j++) acc[m][n][j] = 0.f;

    float4 rA[4];
    float4 rB[2 * BS];
    int arow = tid >> 1;
    int ah16 = (tid & 1) * 16;

    auto ldgTile = [&](int t) {
        int p = t / ktiles;
        int kt = (t - p * ktiles) * 32;
        const float* A = P.A[p];
        const float* W = P.W[p];
        int row = rowBase + arow;
        if (row >= P.M) row = P.M - 1;
        const float* ap = A + (long)row * K + kt + ah16;
        rA[0] = __ldg((const float4*)ap);
        rA[1] = __ldg((const float4*)(ap + 4));
        rA[2] = __ldg((const float4*)(ap + 8));
        rA[3] = __ldg((const float4*)(ap + 12));
#pragma unroll
        for (int s = 0; s < BS; s++) {
            int slot = tid + s * 256;
            int kp = slot & 15, ng = slot >> 4;
            const float* wp = W + (long)(kt + 2 * kp) * BN + ng * 4;
            rB[2 * s] = __ldg((const float4*)wp);
            rB[2 * s + 1] = __ldg((const float4*)(wp + BN));
        }
    };

    auto stsTile = [&](int buf) {
        uint16_t* base = smb + buf * BUFE;
        uint16_t* Ahi = base;
        uint16_t* Alo = base + APLANE;
        uint16_t* Bhi = base + 2 * APLANE;
        uint16_t* Blo = Bhi + BPLANE;
        float x[16];
        *(float4*)&x[0] = rA[0];
        *(float4*)&x[4] = rA[1];
        *(float4*)&x[8] = rA[2];
        *(float4*)&x[12] = rA[3];
        uint32_t hp[8], lp[8];
#pragma unroll
        for (int j = 0; j < 8; j++) split2(x[2 * j], x[2 * j + 1], hp[j], lp[j]);
        *(uint4*)&Ahi[arow * LDK + ah16] = *(uint4*)&hp[0];
        *(uint4*)&Ahi[arow * LDK + ah16 + 8] = *(uint4*)&hp[4];
        *(uint4*)&Alo[arow * LDK + ah16] = *(uint4*)&lp[0];
        *(uint4*)&Alo[arow * LDK + ah16 + 8] = *(uint4*)&lp[4];
#pragma unroll
        for (int s = 0; s < BS; s++) {
            int slot = tid + s * 256;
            int kp = slot & 15, ng = slot >> 4;
            float w0[4], w1[4];
            *(float4*)w0 = rB[2 * s];
            *(float4*)w1 = rB[2 * s + 1];
#pragma unroll
            for (int i = 0; i < 4; i++) {
                uint32_t h, l;
                split2(w0[i], w1[i], h, l);
                int n = ng * 4 + i;
                *(uint32_t*)&Bhi[n * LDK + 2 * kp] = h;
                *(uint32_t*)&Blo[n * LDK + 2 * kp] = l;
            }
        }
    };

    auto compute = [&](int buf) {
        uint16_t* base = smb + buf * BUFE;
        uint16_t* Ahi = base;
        uint16_t* Alo = base + APLANE;
        uint16_t* Bhi = base + 2 * APLANE;
        uint16_t* Blo = Bhi + BPLANE;
#pragma unroll
        for (int c = 0; c < 2; c++) {
            uint32_t ah[2][4], al[2][4], bh[NS][2], bl[NS][2];
#pragma unroll
            for (int m = 0; m < 2; m++) {
                int ro = (wm * 32 + m * 16 + tq) * LDK + c * 16 + tr * 2;
                ah[m][0] = *(const uint32_t*)&Ahi[ro];
                ah[m][1] = *(const uint32_t*)&Ahi[ro + 8 * LDK];
                ah[m][2] = *(const uint32_t*)&Ahi[ro + 8];
                ah[m][3] = *(const uint32_t*)&Ahi[ro + 8 * LDK + 8];
                al[m][0] = *(const uint32_t*)&Alo[ro];
                al[m][1] = *(const uint32_t*)&Alo[ro + 8 * LDK];
                al[m][2] = *(const uint32_t*)&Alo[ro + 8];
                al[m][3] = *(const uint32_t*)&Alo[ro + 8 * LDK + 8];
            }
#pragma unroll
            for (int n = 0; n < NS; n++) {
                int bo = (wn * WN + n * 8 + tq) * LDK + c * 16 + tr * 2;
                bh[n][0] = *(const uint32_t*)&Bhi[bo];
                bh[n][1] = *(const uint32_t*)&Bhi[bo + 8];
                bl[n][0] = *(const uint32_t*)&Blo[bo];
                bl[n][1] = *(const uint32_t*)&Blo[bo + 8];
            }
#pragma unroll
            for (int m = 0; m < 2; m++)
#pragma unroll
                for (int n = 0; n < NS; n++) {
                    MMA_BF16(acc[m][n], ah[m], bh[n]);
                    MMA_BF16(acc[m][n], ah[m], bl[n]);
                    MMA_BF16(acc[m][n], al[m], bh[n]);
                }
        }
    };

    ldgTile(0);
    for (int t = 0; t < T; t++) {
        int buf = t & 1;
        stsTile(buf);
        if (t + 1 < T) ldgTile(t + 1);
        __syncthreads();
        compute(buf);
    }

    // ---- epilogue: bias, BN partials, store ----
    float ls[NS][2], lq[NS][2];
#pragma unroll
    for (int n = 0; n < NS; n++) { ls[n][0] = ls[n][1] = lq[n][0] = lq[n][1] = 0.f; }

#pragma unroll
    for (int m = 0; m < 2; m++) {
        int row0 = rowBase + wm * 32 + m * 16 + tq;
        bool v0 = row0 < P.M;
        bool v1 = (row0 + 8) < P.M;
#pragma unroll
        for (int n = 0; n < NS; n++) {
            int c0 = wn * WN + n * 8 + tr * 2;
            float bb0 = __ldg(&P.bias[c0]);
            float bb1 = __ldg(&P.bias[c0 + 1]);
            float d0 = acc[m][n][0] + bb0;
            float d1 = acc[m][n][1] + bb1;
            float d2 = acc[m][n][2] + bb0;
            float d3 = acc[m][n][3] + bb1;
            if (v0) {
                ls[n][0] += d0; ls[n][1] += d1;
                lq[n][0] = fmaf(d0, d0, lq[n][0]);
                lq[n][1] = fmaf(d1, d1, lq[n][1]);
                float2 o = make_float2(d0, d1);
                *(float2*)&P.C[(long)row0 * BN + c0] = o;
            }
            if (v1) {
                ls[n][0] += d2; ls[n][1] += d3;
                lq[n][0] = fmaf(d2, d2, lq[n][0]);
                lq[n][1] = fmaf(d3, d3, lq[n][1]);
                float2 o = make_float2(d2, d3);
                *(float2*)&P.C[(long)(row0 + 8) * BN + c0] = o;
            }
        }
    }

    if (P.statS) {
#pragma unroll
        for (int n = 0; n < NS; n++) {
#pragma unroll
            for (int h = 0; h < 2; h++) {
                float s = ls[n][h], q = lq[n][h];
#pragma unroll
                for (int o = 4; o < 32; o <<= 1) {
                    s += __shfl_xor_sync(0xFFFFFFFFu, s, o);
                    q += __shfl_xor_sync(0xFFFFFFFFu, q, o);
                }
                if (tq == 0) {
                    int c = wn * WN + n * 8 + tr * 2 + h;
                    atomicAdd(&sS[c], s);
                    atomicAdd(&sQ[c], q);
                }
            }
        }
        __syncthreads();
        if (tid < BN) {
            atomicAdd(&P.statS[tid], sS[tid]);
            atomicAdd(&P.statQ[tid], sQ[tid]);
        }
    }
}

// ---------------- BatchNorm ----------------
__global__ void k_bn_fin2(const float* __restrict__ stat, float Mg, float Md,
                          const float* __restrict__ g, const float* __restrict__ b,
                          float* __restrict__ scale2, float* __restrict__ shift2) {
    int tid = threadIdx.x;
    int t = tid >> 7, c = tid & 127;
    float Mf = t ? Md : Mg;
    float sum = stat[t * 256 + c];
    float sq = stat[t * 256 + 128 + c];
    float mu = sum / Mf;
    float var = sq / Mf - mu * mu;
    float sc = g[t * 128 + c] * rsqrtf(var + 1e-5f);
    scale2[t * 128 + c] = sc;
    shift2[t * 128 + c] = b[t * 128 + c] - mu * sc;
}

__global__ void k_bn_relu2(float* __restrict__ Xg, float* __restrict__ Xd,
                           int nG4, int nD4, const float* __restrict__ scale2,
                           const float* __restrict__ shift2) {
    int i = blockIdx.x * blockDim.x + threadIdx.x;
    float* X;
    int li, t;
    if (i < nG4) { X = Xg; li = i; t = 0; }
    else if (i < nG4 + nD4) { X = Xd; li = i - nG4; t = 1; }
    else return;
    float4 v = ((float4*)X)[li];
    int c = t * 128 + (li & 31) * 4;
    v.x = fmaxf(0.f, fmaf(v.x, __ldg(&scale2[c + 0]), __ldg(&shift2[c + 0])));
    v.y = fmaxf(0.f, fmaf(v.y, __ldg(&scale2[c + 1]), __ldg(&shift2[c + 1])));
    v.z = fmaxf(0.f, fmaf(v.z, __ldg(&scale2[c + 2]), __ldg(&shift2[c + 2])));
    v.w = fmaxf(0.f, fmaf(v.w, __ldg(&scale2[c + 3]), __ldg(&shift2[c + 3])));
    ((float4*)X)[li] = v;
}

// ---------------- host side ----------------
template <typename T>
static T* sym(const void* s) {
    void* p = nullptr;
    cudaGetSymbolAddress(&p, s);
    return (T*)p;
}

extern "C" void kernel_launch(void* const* d_in, const int* in_sizes, int n_in,
                              void* d_out, int out_size) {
    const float* xg  = (const float*)d_in[0];
    const float* xd  = (const float*)d_in[1];
    const float* Wn0 = (const float*)d_in[2];
    const float* Ws0 = (const float*)d_in[3];
    const float* b0  = (const float*)d_in[4];
    const float* Wn1 = (const float*)d_in[5];
    const float* Ws1 = (const float*)d_in[6];
    const float* b1  = (const float*)d_in[7];
    const float* bng = (const float*)d_in[8];
    const float* bnb = (const float*)d_in[9];
    const float* Wpm = (const float*)d_in[10];
    const float* bp  = (const float*)d_in[11];
    const int* gg_src = (const int*)d_in[12];
    const int* gg_dst = (const int*)d_in[13];
    const int* gd_src = (const int*)d_in[14];
    const int* gd_dst = (const int*)d_in[15];
    const int* dg_src = (const int*)d_in[16];
    const int* dg_dst = (const int*)d_in[17];

    const int NG = in_sizes[0] / INF;
    const int ND = in_sizes[1] / INF;
    const int egg = in_sizes[12];
    const int egd = in_sizes[14];
    const int edg = in_sizes[16];

    float* out = (float*)d_out;

    int* cnt = sym<int>(g_cnt);
    int* pos = sym<int>(g_pos);
    int* rp = sym<int>(g_rp);
    int* col_gg = sym<int>(g_col_gg);
    int* col_dg = sym<int>(g_col_dg);
    int* col_gd = sym<int>(g_col_gd);
    int* part = sym<int>(g_part);
    float* mgg = sym<float>(g_mgg);
    float* mdg = sym<float>(g_mdg);
    float* mgd = sym<float>(g_mgd);
    float* hgA = sym<float>(g_hgA);
    float* hdA = sym<float>(g_hdA);
    float* hgB = sym<float>(g_hgB);
    float* hdB = sym<float>(g_hdB);
    float* Wself0 = sym<float>(g_Wself0);
    float* Wself1 = sym<float>(g_Wself1);
    float* bsum0 = sym<float>(g_bsum0);
    float* bsum1 = sym<float>(g_bsum1);
    float* stat = sym<float>(g_stat);
    float* scale = sym<float>(g_scale);
    float* shift = sym<float>(g_shift);

    auto cdiv = [](int a, int b) { return (a + b - 1) / b; };

    int* rp_gg = rp;
    int* rp_dg = rp + NG + 1;
    int* rp_gd = rp + 2 * NG + 2;

    // dynamic smem: double-buffered bf16 hi/lo A(128x32) + B(32xBN) tiles
    const int smem128 = 2 * (2 * 128 * 40 + 2 * 128 * 40) * 2;  // 81920 B
    const int smem64  = 2 * (2 * 128 * 40 + 2 * 64 * 40) * 2;   // 61440 B
    cudaFuncSetAttribute(k_gemm_mma<HIDF>, cudaFuncAttributeMaxDynamicSharedMemorySize, smem128);
    cudaFuncSetAttribute(k_gemm_mma<INF>, cudaFuncAttributeMaxDynamicSharedMemorySize, smem64);

    // --- prep (zero counters/stats + weight sums) ---
    k_prep<<<cdiv(2 * NG + ND, 256), 256>>>(Ws0, Ws1, b0, b1, Wself0, Wself1,
                                            bsum0, bsum1, cnt, 2 * NG + ND, stat);

    // --- fused 3-relation CSR build ---
    int etot = egg + edg + egd;
    k_hist3<<<cdiv(etot, 256), 256>>>(gg_dst, dg_dst, gd_dst, egg, edg, egd, NG, NG, cnt);
    int nb0 = cdiv(NG, 1024), nb1 = cdiv(NG, 1024), nb2 = cdiv(ND, 1024);
    k_scan_part3<<<nb0 + nb1 + nb2, 1024>>>(cnt, NG, NG, ND, nb0, nb1, part);
    k_scan_mid3<<<3, 64>>>(part, nb0, nb1, nb2, NG, NG, ND, rp);
    k_scan_final3<<<nb0 + nb1 + nb2, 1024>>>(cnt, NG, NG, ND, nb0, nb1, part, rp, pos);
    k_scatter3<<<cdiv(etot, 256), 256>>>(gg_src, gg_dst, dg_src, dg_dst, gd_src, gd_dst,
                                         egg, edg, egd, NG, NG, pos, col_gg, col_dg, col_gd);

    int nbG = cdiv(NG, 128);
    int nbD = cdiv(ND, 128);

    // ---------- layer 0 aggregation (F = 64) ----------
    {
        constexpr int gpb = 256 / (INF / 4);
        AggRel a{xg, rp_gg, col_gg, mgg, NG};
        AggRel b{xd, rp_dg, col_dg, mdg, NG};
        AggRel c{xg, rp_gd, col_gd, mgd, ND};
        int na = cdiv(NG, gpb), nbk = cdiv(NG, gpb), nc = cdiv(ND, gpb);
        k_agg3<INF><<<na + nbk + nc, 256>>>(a, b, c, na, na + nbk);
    }

    // ---------- layer 0 GEMM (K=64, N=128) + fused BN stats ----------
    {
        GemmProb pg, pd;
        pg.A[0] = mgg; pg.A[1] = mdg; pg.A[2] = xg;
        pg.W[0] = Wn0; pg.W[1] = Wn0 + 2 * INF * HIDF; pg.W[2] = Wself0;
        pg.bias = bsum0; pg.C = hgA; pg.M = NG; pg.K = INF; pg.npan = 3;
        pg.statS = stat; pg.statQ = stat + 128;
        pd.A[0] = mgd; pd.A[1] = xd; pd.A[2] = nullptr;
        pd.W[0] = Wn0 + INF * HIDF; pd.W[1] = Ws0 + INF * HIDF; pd.W[2] = nullptr;
        pd.bias = b0 + HIDF; pd.C = hdA; pd.M = ND; pd.K = INF; pd.npan = 2;
        pd.statS = stat + 256; pd.statQ = stat + 384;
        k_gemm_mma<HIDF><<<nbG + nbD, 256, smem128>>>(pg, pd, nbG);
    }
    k_bn_fin2<<<1, 256>>>(stat, (float)NG, (float)ND, bng, bnb, scale, shift);
    {
        int nG4 = NG * HIDF / 4, nD4 = ND * HIDF / 4;
        k_bn_relu2<<<cdiv(nG4 + nD4, 256), 256>>>(hgA, hdA, nG4, nD4, scale, shift);
    }

    // ---------- layer 1 aggregation (F = 128) ----------
    {
        constexpr int gpb = 256 / (HIDF / 4);
        AggRel a{hgA, rp_gg, col_gg, mgg, NG};
        AggRel b{hdA, rp_dg, col_dg, mdg, NG};
        AggRel c{hgA, rp_gd, col_gd, mgd, ND};
        int na = cdiv(NG, gpb), nbk = cdiv(NG, gpb), nc = cdiv(ND, gpb);
        k_agg3<HIDF><<<na + nbk + nc, 256>>>(a, b, c, na, na + nbk);
    }

    // ---------- layer 1 GEMM (K=128, N=128) + fused BN stats ----------
    {
        GemmProb pg, pd;
        pg.A[0] = mgg; pg.A[1] = mdg; pg.A[2] = hgA;
        pg.W[0] = Wn1; pg.W[1] = Wn1 + 2 * HIDF * HIDF; pg.W[2] = Wself1;
        pg.bias = bsum1; pg.C = hgB; pg.M = NG; pg.K = HIDF; pg.npan = 3;
        pg.statS = stat + 512; pg.statQ = stat + 640;
        pd.A[0] = mgd; pd.A[1] = hdA; pd.A[2] = nullptr;
        pd.W[0] = Wn1 + HIDF * HIDF; pd.W[1] = Ws1 + HIDF * HIDF; pd.W[2] = nullptr;
        pd.bias = b1 + HIDF; pd.C = hdB; pd.M = ND; pd.K = HIDF; pd.npan = 2;
        pd.statS = stat + 768; pd.statQ = stat + 896;
        k_gemm_mma<HIDF><<<nbG + nbD, 256, smem128>>>(pg, pd, nbG);
    }
    k_bn_fin2<<<1, 256>>>(stat + 512, (float)NG, (float)ND, bng + 256, bnb + 256, scale, shift);
    {
        int nG4 = NG * HIDF / 4, nD4 = ND * HIDF / 4;
        k_bn_relu2<<<cdiv(nG4 + nD4, 256), 256>>>(hgB, hdB, nG4, nD4, scale, shift);
    }

    // ---------- final projection (K=128, N=64) ----------
    {
        GemmProb pg, pd;
        pg.A[0] = hgB; pg.A[1] = nullptr; pg.A[2] = nullptr;
        pg.W[0] = Wpm; pg.W[1] = nullptr; pg.W[2] = nullptr;
        pg.bias = bp; pg.C = out; pg.M = NG; pg.K = HIDF; pg.npan = 1;
        pg.statS = nullptr; pg.statQ = nullptr;
        pd.A[0] = hdB; pd.A[1] = nullptr; pd.A[2] = nullptr;
        pd.W[0] = Wpm + HIDF * INF; pd.W[1] = nullptr; pd.W[2] = nullptr;
        pd.bias = bp + INF; pd.C = out + (long)NG * INF; pd.M = ND; pd.K = HIDF; pd.npan = 1;
        pd.statS = nullptr; pd.statQ = nullptr;
        k_gemm_mma<INF><<<nbG + nbD, 256, smem64>>>(pg, pd, nbG);
    }
}